// round 5
// baseline (speedup 1.0000x reference)
#include <cuda_runtime.h>
#include <cuda_bf16.h>
#include <math.h>

#define BB 8192
#define FF 24
#define VV 100000
#define DD 64
#define PP 276  // FF*(FF-1)/2

// Scratch (allocation-free rule: __device__ globals)
__device__ uint2 g_wpk[PP];  // {bf16x2 splat wMul, bf16x2 splat wD}
__device__ float g_cA[FF];   // per-field coefficient for the s_plus term

// ---------------------------------------------------------------------------
// Prep: fold arch_w (+flag semantics) into bf16x2 pair weights + fp32 cA.
//   t_p = wS*s_plus + wMul*s_mul + wD*s_absdiff
//   wS = w0 + w4 + 0.5*(w2+w3);  wMul = w1;  wD = 0.5*(w2-w3)
//   flag==0 == flag==1 with one-hot(argmax) weights.
// ---------------------------------------------------------------------------
__global__ void ofm_prep_kernel(const float* __restrict__ arch_w,
                                const int* __restrict__ flagp) {
    int t = threadIdx.x;
    if (t < FF) g_cA[t] = 0.0f;
    __syncthreads();
    if (t < PP) {
        int i = 1, p = t;
        while (p >= i) { p -= i; i++; }
        int j = p;

        float w[5];
#pragma unroll
        for (int k = 0; k < 5; k++) w[k] = arch_w[t * 5 + k];

        if (*flagp == 0) {
            int sel = 0;
            float best = w[0];
#pragma unroll
            for (int k = 1; k < 5; k++)
                if (w[k] > best) { best = w[k]; sel = k; }
#pragma unroll
            for (int k = 0; k < 5; k++) w[k] = (k == sel) ? 1.0f : 0.0f;
        }

        float wS = w[0] + w[4] + 0.5f * (w[2] + w[3]);
        float wD = 0.5f * (w[2] - w[3]);

        __nv_bfloat162 m2 = __float2bfloat162_rn(w[1]);
        __nv_bfloat162 d2 = __float2bfloat162_rn(wD);
        g_wpk[t] = make_uint2(*reinterpret_cast<unsigned*>(&m2),
                              *reinterpret_cast<unsigned*>(&d2));
        atomicAdd(&g_cA[i], wS);
        atomicAdd(&g_cA[j], wS);
    }
}

// ---------------------------------------------------------------------------
// Pair loop for one row (bf16x2 tile in eb[]): returns mul+absdiff total.
// 4 fma-pipe ops/pair + 1 alu AND; bf16x2 partials flushed to fp32 per
// i-row (<=23 adds) to bound accumulation error.
// ---------------------------------------------------------------------------
static __device__ __forceinline__ float pair_loop(
    const __nv_bfloat162* eb, const uint2* s_w) {
    float accM = 0.0f, accA = 0.0f;
#pragma unroll
    for (int i = 1; i < FF; i++) {
        unsigned aM = 0u, aA = 0u;
#pragma unroll
        for (int j = 0; j < i; j++) {
            const int p = i * (i - 1) / 2 + j;
            uint2 wraw = s_w[p];  // broadcast LDS.64
            __nv_bfloat162 wm = *reinterpret_cast<__nv_bfloat162*>(&wraw.x);
            __nv_bfloat162 wd = *reinterpret_cast<__nv_bfloat162*>(&wraw.y);

            __nv_bfloat162 prod = __hmul2(eb[i], eb[j]);
            __nv_bfloat162 am = *reinterpret_cast<__nv_bfloat162*>(&aM);
            am = __hfma2(wm, prod, am);
            aM = *reinterpret_cast<unsigned*>(&am);

            __nv_bfloat162 dif = __hsub2(eb[i], eb[j]);
            unsigned ud = *reinterpret_cast<unsigned*>(&dif) & 0x7FFF7FFFu;
            __nv_bfloat162 ad = *reinterpret_cast<__nv_bfloat162*>(&ud);
            __nv_bfloat162 aa = *reinterpret_cast<__nv_bfloat162*>(&aA);
            aa = __hfma2(wd, ad, aa);
            aA = *reinterpret_cast<unsigned*>(&aa);
        }
        accM += __uint_as_float(aM << 16) + __uint_as_float(aM & 0xFFFF0000u);
        accA += __uint_as_float(aA << 16) + __uint_as_float(aA & 0xFFFF0000u);
    }
    return accM + accA;
}

// ---------------------------------------------------------------------------
// Main kernel: one warp per TWO rows, processed SEQUENTIALLY with a one-row
// register lookahead: row1's 24 e2 loads are issued before row0's pair loop
// (~2500 cyc of compute in flight over the DRAM gather). x/emb1 for both
// rows load in the prologue, so the two-deep dependent gather chain
// (x -> shfl -> e2) is only exposed once per warp.
// ---------------------------------------------------------------------------
__global__ __launch_bounds__(256, 2) void ofm_main_kernel(
    const int* __restrict__ x,
    const float* __restrict__ emb2,
    const float* __restrict__ emb1,
    const float* __restrict__ bias,
    float* __restrict__ out) {

    __shared__ uint2 s_w[PP];
    __shared__ float s_cA[FF];

    int tid = threadIdx.x;
    for (int k = tid; k < PP; k += 256)
        s_w[k] = g_wpk[k];
    if (tid < FF) s_cA[tid] = g_cA[tid];
    __syncthreads();

    int warp = tid >> 5;
    int lane = tid & 31;
    int row0 = blockIdx.x * 16 + warp * 2;  // BB % 16 == 0
    int row1 = row0 + 1;

    // Prologue: x + emb1 for BOTH rows (lanes 0..23)
    int xv0 = 0, xv1 = 0;
    float e1v0 = 0.0f, e1v1 = 0.0f;
    if (lane < FF) {
        xv0 = x[row0 * FF + lane];
        xv1 = x[row1 * FF + lane];
        e1v0 = emb1[(size_t)lane * VV + xv0];
        e1v1 = emb1[(size_t)lane * VV + xv1];
    }

    // Tile A (row0) f32 loads — 24 independent 256B-coalesced LDG.64
    float2 fa[FF];
#pragma unroll
    for (int f = 0; f < FF; f++) {
        int xf = __shfl_sync(0xffffffffu, xv0, f);
        fa[f] = __ldg(reinterpret_cast<const float2*>(
                          emb2 + ((size_t)f * VV + xf) * DD) + lane);
    }

    // Convert A -> bf16x2 tile + fp32 s_plus for row0
    __nv_bfloat162 eb[FF];
    float splus0 = (lane < FF) ? e1v0 : 0.0f;
#pragma unroll
    for (int f = 0; f < FF; f++) {
        splus0 = fmaf(s_cA[f], fa[f].x + fa[f].y, splus0);
        eb[f] = __float22bfloat162_rn(fa[f]);
    }

    // PREFETCH: issue tile B (row1) loads before row0's compute
    float2 fb[FF];
#pragma unroll
    for (int f = 0; f < FF; f++) {
        int xf = __shfl_sync(0xffffffffu, xv1, f);
        fb[f] = __ldg(reinterpret_cast<const float2*>(
                          emb2 + ((size_t)f * VV + xf) * DD) + lane);
    }

    // Row 0 compute (tile B gather in flight underneath)
    float acc0 = splus0 + pair_loop(eb, s_w);
#pragma unroll
    for (int o = 16; o; o >>= 1)
        acc0 += __shfl_xor_sync(0xffffffffu, acc0, o);
    if (lane == 0)
        out[row0] = 1.0f / (1.0f + expf(-(acc0 + bias[0])));

    // Convert B -> bf16x2 tile + fp32 s_plus for row1
    float splus1 = (lane < FF) ? e1v1 : 0.0f;
#pragma unroll
    for (int f = 0; f < FF; f++) {
        splus1 = fmaf(s_cA[f], fb[f].x + fb[f].y, splus1);
        eb[f] = __float22bfloat162_rn(fb[f]);
    }

    // Row 1 compute
    float acc1 = splus1 + pair_loop(eb, s_w);
#pragma unroll
    for (int o = 16; o; o >>= 1)
        acc1 += __shfl_xor_sync(0xffffffffu, acc1, o);
    if (lane == 0)
        out[row1] = 1.0f / (1.0f + expf(-(acc1 + bias[0])));
}

// ---------------------------------------------------------------------------
// d_in order: 0=x(int32 B*F), 1=flag(int32), 2=emb2(f32 F*V*D),
//             3=emb1(f32 F*V), 4=bias(f32 1), 5=arch_w(f32 P*5)
// ---------------------------------------------------------------------------
extern "C" void kernel_launch(void* const* d_in, const int* in_sizes, int n_in,
                              void* d_out, int out_size) {
    const int* x = (const int*)d_in[0];
    const int* flag = (const int*)d_in[1];
    const float* emb2 = (const float*)d_in[2];
    const float* emb1 = (const float*)d_in[3];
    const float* bias = (const float*)d_in[4];
    const float* arch_w = (const float*)d_in[5];
    float* out = (float*)d_out;

    ofm_prep_kernel<<<1, 288>>>(arch_w, flag);
    ofm_main_kernel<<<BB / 16, 256>>>(x, emb2, emb1, bias, out);
}

// round 6
// speedup vs baseline: 11.6074x; 11.6074x over previous
#include <cuda_runtime.h>
#include <cuda_bf16.h>
#include <math.h>

#define BB 8192
#define FF 24
#define VV 100000
#define DD 64
#define PP 276  // FF*(FF-1)/2

// Scratch (allocation-free rule: __device__ globals)
__device__ uint2 g_wpk[PP];  // {bf16x2 splat wMul, bf16x2 splat wD}
__device__ float g_cA[FF];   // per-field coefficient for the s_plus term

// ---------------------------------------------------------------------------
// Prep: fold arch_w (+flag semantics) into bf16x2 pair weights + fp32 cA.
//   t_p = wS*s_plus + wMul*s_mul + wD*s_absdiff
//   wS = w0 + w4 + 0.5*(w2+w3);  wMul = w1;  wD = 0.5*(w2-w3)
//   flag==0 == flag==1 with one-hot(argmax) weights.
// ---------------------------------------------------------------------------
__global__ void ofm_prep_kernel(const float* __restrict__ arch_w,
                                const int* __restrict__ flagp) {
    int t = threadIdx.x;
    if (t < FF) g_cA[t] = 0.0f;
    __syncthreads();
    if (t < PP) {
        int i = 1, p = t;
        while (p >= i) { p -= i; i++; }
        int j = p;

        float w[5];
#pragma unroll
        for (int k = 0; k < 5; k++) w[k] = arch_w[t * 5 + k];

        if (*flagp == 0) {
            int sel = 0;
            float best = w[0];
#pragma unroll
            for (int k = 1; k < 5; k++)
                if (w[k] > best) { best = w[k]; sel = k; }
#pragma unroll
            for (int k = 0; k < 5; k++) w[k] = (k == sel) ? 1.0f : 0.0f;
        }

        float wS = w[0] + w[4] + 0.5f * (w[2] + w[3]);
        float wD = 0.5f * (w[2] - w[3]);

        __nv_bfloat162 m2 = __float2bfloat162_rn(w[1]);
        __nv_bfloat162 d2 = __float2bfloat162_rn(wD);
        g_wpk[t] = make_uint2(*reinterpret_cast<unsigned*>(&m2),
                              *reinterpret_cast<unsigned*>(&d2));
        atomicAdd(&g_cA[i], wS);
        atomicAdd(&g_cA[j], wS);
    }
}

// ---------------------------------------------------------------------------
// Pair loop for one row (bf16x2 tile in eb[]): 4 fma-pipe ops/pair + 1 alu
// AND; bf16x2 partials flushed to fp32 per i-row (<=23 adds).  (Identical to
// the verified round-3 math: rel_err 4.4e-6.)
// ---------------------------------------------------------------------------
static __device__ __forceinline__ float pair_loop(
    const __nv_bfloat162* eb, const uint2* s_w) {
    float accM = 0.0f, accA = 0.0f;
#pragma unroll
    for (int i = 1; i < FF; i++) {
        unsigned aM = 0u, aA = 0u;
#pragma unroll
        for (int j = 0; j < i; j++) {
            const int p = i * (i - 1) / 2 + j;
            uint2 wraw = s_w[p];  // broadcast LDS.64
            __nv_bfloat162 wm = *reinterpret_cast<__nv_bfloat162*>(&wraw.x);
            __nv_bfloat162 wd = *reinterpret_cast<__nv_bfloat162*>(&wraw.y);

            __nv_bfloat162 prod = __hmul2(eb[i], eb[j]);
            __nv_bfloat162 am = *reinterpret_cast<__nv_bfloat162*>(&aM);
            am = __hfma2(wm, prod, am);
            aM = *reinterpret_cast<unsigned*>(&am);

            __nv_bfloat162 dif = __hsub2(eb[i], eb[j]);
            unsigned ud = *reinterpret_cast<unsigned*>(&dif) & 0x7FFF7FFFu;
            __nv_bfloat162 ad = *reinterpret_cast<__nv_bfloat162*>(&ud);
            __nv_bfloat162 aa = *reinterpret_cast<__nv_bfloat162*>(&aA);
            aa = __hfma2(wd, ad, aa);
            aA = *reinterpret_cast<unsigned*>(&aa);
        }
        accM += __uint_as_float(aM << 16) + __uint_as_float(aM & 0xFFFF0000u);
        accA += __uint_as_float(aA << 16) + __uint_as_float(aA & 0xFFFF0000u);
    }
    return accM + accA;
}

// ---------------------------------------------------------------------------
// Main kernel: one warp per TWO rows. Row1's e2 tile is prefetched to SHARED
// MEMORY via cp.async (zero register cost — round 5's register-resident
// lookahead spilled at 128 regs) while row0 runs the round-3 gather+compute
// path. 12 x 16B LDGSTS per row tile, single 6KB/warp stage buffer.
// ---------------------------------------------------------------------------
__global__ __launch_bounds__(256, 4) void ofm_main_kernel(
    const int* __restrict__ x,
    const float* __restrict__ emb2,
    const float* __restrict__ emb1,
    const float* __restrict__ bias,
    float* __restrict__ out) {

    __shared__ float s_stage[8][FF * DD];  // 8 warps x 6KB
    __shared__ uint2 s_w[PP];
    __shared__ float s_cA[FF];

    int tid = threadIdx.x;
    for (int k = tid; k < PP; k += 256)
        s_w[k] = g_wpk[k];
    if (tid < FF) s_cA[tid] = g_cA[tid];
    __syncthreads();

    int warp = tid >> 5;
    int lane = tid & 31;
    int row0 = blockIdx.x * 16 + warp * 2;  // BB % 16 == 0
    int row1 = row0 + 1;
    float* stage = s_stage[warp];

    // Prologue: x + emb1 for BOTH rows (lanes 0..23)
    int xv0 = 0, xv1 = 0;
    float e1v0 = 0.0f, e1v1 = 0.0f;
    if (lane < FF) {
        xv0 = x[row0 * FF + lane];
        xv1 = x[row1 * FF + lane];
        e1v0 = emb1[(size_t)lane * VV + xv0];
        e1v1 = emb1[(size_t)lane * VV + xv1];
    }

    // PREFETCH row1 tile gmem->smem via cp.async: 12 x (2 fields x 16 lanes
    // x 16B). No registers hold the data.
    {
        int chunk = lane & 15;           // 16B chunk within a field row
        int fhalf = lane >> 4;           // 0 or 1: which field of the pair
#pragma unroll
        for (int h = 0; h < 12; h++) {
            int f = 2 * h + fhalf;
            int xf = __shfl_sync(0xffffffffu, xv1, f);
            const float* src = emb2 + ((size_t)f * VV + xf) * DD + chunk * 4;
            unsigned dst = (unsigned)__cvta_generic_to_shared(
                stage + f * DD + chunk * 4);
            asm volatile("cp.async.cg.shared.global [%0], [%1], 16;"
                         :: "r"(dst), "l"(src));
        }
        asm volatile("cp.async.commit_group;");
    }

    // Row0: direct gather + convert (round-3 path); cp.async lands underneath
    __nv_bfloat162 eb[FF];
    float splus0 = (lane < FF) ? e1v0 : 0.0f;
#pragma unroll
    for (int f = 0; f < FF; f++) {
        int xf = __shfl_sync(0xffffffffu, xv0, f);
        float2 v = __ldg(reinterpret_cast<const float2*>(
                             emb2 + ((size_t)f * VV + xf) * DD) + lane);
        splus0 = fmaf(s_cA[f], v.x + v.y, splus0);
        eb[f] = __float22bfloat162_rn(v);
    }

    float acc0 = splus0 + pair_loop(eb, s_w);
#pragma unroll
    for (int o = 16; o; o >>= 1)
        acc0 += __shfl_xor_sync(0xffffffffu, acc0, o);
    if (lane == 0)
        out[row0] = 1.0f / (1.0f + expf(-(acc0 + bias[0])));

    // Row1: tile is (long since) in smem
    asm volatile("cp.async.wait_group 0;");
    __syncwarp();

    float splus1 = (lane < FF) ? e1v1 : 0.0f;
#pragma unroll
    for (int f = 0; f < FF; f++) {
        float2 v = *reinterpret_cast<const float2*>(stage + f * DD + 2 * lane);
        splus1 = fmaf(s_cA[f], v.x + v.y, splus1);
        eb[f] = __float22bfloat162_rn(v);
    }

    float acc1 = splus1 + pair_loop(eb, s_w);
#pragma unroll
    for (int o = 16; o; o >>= 1)
        acc1 += __shfl_xor_sync(0xffffffffu, acc1, o);
    if (lane == 0)
        out[row1] = 1.0f / (1.0f + expf(-(acc1 + bias[0])));
}

// ---------------------------------------------------------------------------
// d_in order: 0=x(int32 B*F), 1=flag(int32), 2=emb2(f32 F*V*D),
//             3=emb1(f32 F*V), 4=bias(f32 1), 5=arch_w(f32 P*5)
// ---------------------------------------------------------------------------
extern "C" void kernel_launch(void* const* d_in, const int* in_sizes, int n_in,
                              void* d_out, int out_size) {
    const int* x = (const int*)d_in[0];
    const int* flag = (const int*)d_in[1];
    const float* emb2 = (const float*)d_in[2];
    const float* emb1 = (const float*)d_in[3];
    const float* bias = (const float*)d_in[4];
    const float* arch_w = (const float*)d_in[5];
    float* out = (float*)d_out;

    ofm_prep_kernel<<<1, 288>>>(arch_w, flag);
    ofm_main_kernel<<<BB / 16, 256>>>(x, emb2, emb1, bias, out);
}